// round 1
// baseline (speedup 1.0000x reference)
#include <cuda_runtime.h>

#define N_NODES 50000
#define D 128
#define R_REL 8
#define E_EDGES 800000
#define NR (N_NODES * R_REL)   // 400000
#define KTOT 1152              // R*D + D
#define KA 1024                // R*D

// Scratch (allocation-free rule: __device__ globals)
__device__ float g_num[(size_t)N_NODES * 1024];  // [N, R*D] segment accumulator (== update numerator)
__device__ float g_den[NR];                      // per-segment weight sum, then inverted in place

// ---------------------------------------------------------------------------
// Zero the accumulators (must happen every launch; graph replays re-run us)
// ---------------------------------------------------------------------------
__global__ void zero_kernel() {
    const float4 z = make_float4(0.f, 0.f, 0.f, 0.f);
    float4* pn = reinterpret_cast<float4*>(g_num);
    const int n4 = N_NODES * 1024 / 4;
    for (int i = blockIdx.x * blockDim.x + threadIdx.x; i < n4; i += gridDim.x * blockDim.x)
        pn[i] = z;
    float4* pd = reinterpret_cast<float4*>(g_den);
    const int d4 = NR / 4;
    for (int i = blockIdx.x * blockDim.x + threadIdx.x; i < d4; i += gridDim.x * blockDim.x)
        pd[i] = z;
}

// ---------------------------------------------------------------------------
// Edge scatter: warp per edge, float4 per lane, vector reduction atomics
// ---------------------------------------------------------------------------
__global__ void scatter_kernel(const float* __restrict__ x,
                               const float* __restrict__ ew,
                               const int* __restrict__ nin,
                               const int* __restrict__ nout,
                               const int* __restrict__ rel) {
    const int gw = (blockIdx.x * blockDim.x + threadIdx.x) >> 5;
    const int lane = threadIdx.x & 31;
    if (gw >= E_EDGES) return;

    int vin = 0, seg = 0;
    float w = 0.f;
    if (lane == 0) {
        vin = nin[gw];
        seg = nout[gw] * R_REL + rel[gw];
        w = ew[gw];
    }
    vin = __shfl_sync(0xffffffffu, vin, 0);
    seg = __shfl_sync(0xffffffffu, seg, 0);
    w   = __shfl_sync(0xffffffffu, w, 0);

    const float4 xv = *reinterpret_cast<const float4*>(x + (size_t)vin * D + lane * 4);
    float* dst = g_num + (size_t)seg * D + lane * 4;
    asm volatile("red.global.add.v4.f32 [%0], {%1,%2,%3,%4};"
                 :: "l"(dst), "f"(xv.x * w), "f"(xv.y * w), "f"(xv.z * w), "f"(xv.w * w)
                 : "memory");
    if (lane == 0) atomicAdd(g_den + seg, w);
}

// ---------------------------------------------------------------------------
// Invert denominators in place: den <- 1/(den + EPS)
// ---------------------------------------------------------------------------
__global__ void invden_kernel() {
    const int i = blockIdx.x * blockDim.x + threadIdx.x;
    if (i < NR) g_den[i] = 1.0f / (g_den[i] + 1e-10f);
}

// ---------------------------------------------------------------------------
// Fused GEMM: out = relu( [num*invden | x] @ [W_lin ; W_loop] + b_lin + b_loop )
// A is virtual [N, 1152]: cols 0..1023 from g_num (scaled per (row, k/128)),
// cols 1024..1151 from x. BM=BN=128, BK=8, 256 threads, 8x8 per thread.
// ---------------------------------------------------------------------------
__global__ __launch_bounds__(256, 2)
void gemm_kernel(const float* __restrict__ x,
                 const float* __restrict__ Wlin, const float* __restrict__ blin,
                 const float* __restrict__ Wloop, const float* __restrict__ bloop,
                 float* __restrict__ out) {
    __shared__ float As[8][128];
    __shared__ float Bs[8][128];
    __shared__ float invs[128 * 8];   // per-row inverse denominators for this block

    const int tid = threadIdx.x;
    const int n0 = blockIdx.x * 128;

    // Preload inv_den for this block's 128 rows x 8 relations
    for (int i = tid; i < 128 * 8; i += 256) {
        const int row = n0 + (i >> 3);
        invs[i] = (row < N_NODES) ? g_den[row * 8 + (i & 7)] : 0.f;
    }
    __syncthreads();

    // A-load mapping: 128 rows x 8 cols tile = 256 float4s
    const int arow = tid >> 1;            // 0..127
    const int acol = (tid & 1) * 4;       // 0 or 4
    // B-load mapping: 8 rows x 128 cols tile
    const int brow = tid >> 5;            // 0..7
    const int bcol = (tid & 31) * 4;      // 0..124
    // compute mapping: 16x16 thread grid, 8x8 micro-tile
    const int ty = tid >> 4;
    const int tx = tid & 15;

    float acc[8][8];
    #pragma unroll
    for (int i = 0; i < 8; i++)
        #pragma unroll
        for (int j = 0; j < 8; j++) acc[i][j] = 0.f;

    const int grow = n0 + arow;
    const bool rowok = (grow < N_NODES);

    for (int k0 = 0; k0 < KTOT; k0 += 8) {
        // ---- global loads into registers ----
        float4 av = make_float4(0.f, 0.f, 0.f, 0.f);
        if (rowok) {
            if (k0 < KA) {
                av = *reinterpret_cast<const float4*>(g_num + (size_t)grow * 1024 + k0 + acol);
                const float s = invs[(arow << 3) + (k0 >> 7)];
                av.x *= s; av.y *= s; av.z *= s; av.w *= s;
            } else {
                av = *reinterpret_cast<const float4*>(x + (size_t)grow * 128 + (k0 - KA) + acol);
            }
        }
        const int kb = k0 + brow;
        const float* bptr = (kb < KA) ? (Wlin + (size_t)kb * 128 + bcol)
                                      : (Wloop + (size_t)(kb - KA) * 128 + bcol);
        const float4 bv = *reinterpret_cast<const float4*>(bptr);

        __syncthreads();   // previous tile fully consumed
        As[acol + 0][arow] = av.x;
        As[acol + 1][arow] = av.y;
        As[acol + 2][arow] = av.z;
        As[acol + 3][arow] = av.w;
        *reinterpret_cast<float4*>(&Bs[brow][bcol]) = bv;
        __syncthreads();

        // ---- compute ----
        #pragma unroll
        for (int kk = 0; kk < 8; kk++) {
            float a[8], b[8];
            *reinterpret_cast<float4*>(&a[0]) = *reinterpret_cast<const float4*>(&As[kk][ty * 8]);
            *reinterpret_cast<float4*>(&a[4]) = *reinterpret_cast<const float4*>(&As[kk][ty * 8 + 4]);
            *reinterpret_cast<float4*>(&b[0]) = *reinterpret_cast<const float4*>(&Bs[kk][tx * 8]);
            *reinterpret_cast<float4*>(&b[4]) = *reinterpret_cast<const float4*>(&Bs[kk][tx * 8 + 4]);
            #pragma unroll
            for (int i = 0; i < 8; i++)
                #pragma unroll
                for (int j = 0; j < 8; j++)
                    acc[i][j] += a[i] * b[j];
        }
    }

    // ---- epilogue: bias + relu + store ----
    float bias[8];
    #pragma unroll
    for (int j = 0; j < 8; j++) bias[j] = blin[tx * 8 + j] + bloop[tx * 8 + j];

    #pragma unroll
    for (int i = 0; i < 8; i++) {
        const int row = n0 + ty * 8 + i;
        if (row < N_NODES) {
            float4 v0, v1;
            v0.x = fmaxf(acc[i][0] + bias[0], 0.f);
            v0.y = fmaxf(acc[i][1] + bias[1], 0.f);
            v0.z = fmaxf(acc[i][2] + bias[2], 0.f);
            v0.w = fmaxf(acc[i][3] + bias[3], 0.f);
            v1.x = fmaxf(acc[i][4] + bias[4], 0.f);
            v1.y = fmaxf(acc[i][5] + bias[5], 0.f);
            v1.z = fmaxf(acc[i][6] + bias[6], 0.f);
            v1.w = fmaxf(acc[i][7] + bias[7], 0.f);
            *reinterpret_cast<float4*>(out + (size_t)row * 128 + tx * 8) = v0;
            *reinterpret_cast<float4*>(out + (size_t)row * 128 + tx * 8 + 4) = v1;
        }
    }
}

// ---------------------------------------------------------------------------
// Launch: inputs per metadata order:
// 0:x 1:edge_weight 2:W_lin 3:b_lin 4:W_loop 5:b_loop 6:node_in 7:node_out 8:relation
// ---------------------------------------------------------------------------
extern "C" void kernel_launch(void* const* d_in, const int* in_sizes, int n_in,
                              void* d_out, int out_size) {
    const float* x     = (const float*)d_in[0];
    const float* ew    = (const float*)d_in[1];
    const float* Wlin  = (const float*)d_in[2];
    const float* blin  = (const float*)d_in[3];
    const float* Wloop = (const float*)d_in[4];
    const float* bloop = (const float*)d_in[5];
    const int* nin     = (const int*)d_in[6];
    const int* nout    = (const int*)d_in[7];
    const int* rel     = (const int*)d_in[8];
    float* out         = (float*)d_out;

    zero_kernel<<<4096, 256>>>();
    scatter_kernel<<<E_EDGES / 8, 256>>>(x, ew, nin, nout, rel);
    invden_kernel<<<(NR + 255) / 256, 256>>>();
    gemm_kernel<<<(N_NODES + 127) / 128, 256>>>(x, Wlin, blin, Wloop, bloop, out);
}

// round 2
// speedup vs baseline: 2.1405x; 2.1405x over previous
#include <cuda_runtime.h>
#include <cstdint>

#define N_NODES 50000
#define D 128
#define R_REL 8
#define E_EDGES 800000
#define NR (N_NODES * R_REL)   // 400000
#define KTOT 1152              // R*D + D
#define KA 1024                // R*D

// Scratch (allocation-free rule: __device__ globals)
__device__ float g_num[(size_t)N_NODES * 1024];  // [N, R*D] segment accumulator
__device__ float g_den[NR];                      // per-segment weight sum -> inverted in place

// ---------------------------------------------------------------------------
// Zero the accumulators (graph replays re-run us)
// ---------------------------------------------------------------------------
__global__ void zero_kernel() {
    const float4 z = make_float4(0.f, 0.f, 0.f, 0.f);
    float4* pn = reinterpret_cast<float4*>(g_num);
    const int n4 = N_NODES * 1024 / 4;
    for (int i = blockIdx.x * blockDim.x + threadIdx.x; i < n4; i += gridDim.x * blockDim.x)
        pn[i] = z;
    float4* pd = reinterpret_cast<float4*>(g_den);
    const int d4 = NR / 4;
    for (int i = blockIdx.x * blockDim.x + threadIdx.x; i < d4; i += gridDim.x * blockDim.x)
        pd[i] = z;
}

// ---------------------------------------------------------------------------
// Edge scatter: warp per edge, float4 per lane, vector reduction atomics
// ---------------------------------------------------------------------------
__global__ void scatter_kernel(const float* __restrict__ x,
                               const float* __restrict__ ew,
                               const int* __restrict__ nin,
                               const int* __restrict__ nout,
                               const int* __restrict__ rel) {
    const int gw = (blockIdx.x * blockDim.x + threadIdx.x) >> 5;
    const int lane = threadIdx.x & 31;
    if (gw >= E_EDGES) return;

    int vin = 0, seg = 0;
    float w = 0.f;
    if (lane == 0) {
        vin = nin[gw];
        seg = nout[gw] * R_REL + rel[gw];
        w = ew[gw];
    }
    vin = __shfl_sync(0xffffffffu, vin, 0);
    seg = __shfl_sync(0xffffffffu, seg, 0);
    w   = __shfl_sync(0xffffffffu, w, 0);

    const float4 xv = *reinterpret_cast<const float4*>(x + (size_t)vin * D + lane * 4);
    float* dst = g_num + (size_t)seg * D + lane * 4;
    asm volatile("red.global.add.v4.f32 [%0], {%1,%2,%3,%4};"
                 :: "l"(dst), "f"(xv.x * w), "f"(xv.y * w), "f"(xv.z * w), "f"(xv.w * w)
                 : "memory");
    if (lane == 0) atomicAdd(g_den + seg, w);
}

// ---------------------------------------------------------------------------
// den <- 1/(den + EPS)
// ---------------------------------------------------------------------------
__global__ void invden_kernel() {
    const int i = blockIdx.x * blockDim.x + threadIdx.x;
    if (i < NR) g_den[i] = 1.0f / (g_den[i] + 1e-10f);
}

// ---------------------------------------------------------------------------
// TF32 tensor-core GEMM:
// out = relu( [num*invden | x] @ [W_lin ; W_loop] + b_lin + b_loop )
// BM=128, BN=128 (full D), BK=16, 256 threads (8 warps, 2x4 warp grid,
// warp tile 64x32), mma.sync.m16n8k8.tf32, double-buffered smem.
// ---------------------------------------------------------------------------
#define AS_STRIDE 20    // [row][k] layout, stride%32==20 -> conflict-free frag reads
#define BS_STRIDE 136   // [k][n] layout, stride%32==8  -> conflict-free frag reads

__device__ __forceinline__ uint32_t f2tf(float f) {
    uint32_t u;
    asm("cvt.rna.tf32.f32 %0, %1;" : "=r"(u) : "f"(f));
    return u;
}

__global__ __launch_bounds__(256, 2)
void gemm_tf32(const float* __restrict__ x,
               const float* __restrict__ Wlin, const float* __restrict__ blin,
               const float* __restrict__ Wloop, const float* __restrict__ bloop,
               float* __restrict__ out) {
    __shared__ uint32_t As[2][128][AS_STRIDE];
    __shared__ uint32_t Bs[2][16][BS_STRIDE];
    __shared__ float invs[128 * 8];
    __shared__ float bias_s[128];

    const int tid  = threadIdx.x;
    const int n0blk = blockIdx.x * 128;

    for (int i = tid; i < 128 * 8; i += 256) {
        const int row = n0blk + (i >> 3);
        invs[i] = (row < N_NODES) ? g_den[row * 8 + (i & 7)] : 0.f;
    }
    if (tid < 128) bias_s[tid] = blin[tid] + bloop[tid];

    const int lane = tid & 31;
    const int wid  = tid >> 5;
    const int g = lane >> 2;      // 0..7
    const int t = lane & 3;       // 0..3
    const int wm = wid >> 2;      // 0..1  (M warp coord, 64 rows each)
    const int wn = wid & 3;       // 0..3  (N warp coord, 32 cols each)

    // global->smem loader mappings
    const int lrow0 = tid >> 2;          // A local row for j=0 (0..63); j=1 adds 64
    const int ac    = (tid & 3) * 4;     // A col group within BK (0,4,8,12)
    const int bk0   = tid >> 5;          // B k-row for j=0 (0..7); j=1 adds 8
    const int bn    = lane * 4;          // B col (0..124)

    float c[4][4][4];
    #pragma unroll
    for (int mt = 0; mt < 4; mt++)
        #pragma unroll
        for (int nt = 0; nt < 4; nt++)
            #pragma unroll
            for (int q = 0; q < 4; q++) c[mt][nt][q] = 0.f;

    float4 pa[2], pb[2];

    __syncthreads();   // invs ready before first prefetch uses it

#define PREFETCH(K0) do {                                                        \
    _Pragma("unroll")                                                            \
    for (int j = 0; j < 2; j++) {                                                \
        const int lr = lrow0 + 64 * j;                                           \
        const int gr = n0blk + lr;                                               \
        float4 v = make_float4(0.f, 0.f, 0.f, 0.f);                              \
        if (gr < N_NODES) {                                                      \
            if ((K0) < KA) {                                                     \
                v = *reinterpret_cast<const float4*>(                            \
                        g_num + (size_t)gr * 1024 + (K0) + ac);                  \
                const float s = invs[(lr << 3) + ((K0) >> 7)];                   \
                v.x *= s; v.y *= s; v.z *= s; v.w *= s;                          \
            } else {                                                             \
                v = *reinterpret_cast<const float4*>(                            \
                        x + (size_t)gr * 128 + (K0) - KA + ac);                  \
            }                                                                    \
        }                                                                        \
        pa[j] = v;                                                               \
        const int kb = (K0) + bk0 + 8 * j;                                       \
        pb[j] = (kb < KA)                                                        \
            ? *reinterpret_cast<const float4*>(Wlin + (size_t)kb * 128 + bn)     \
            : *reinterpret_cast<const float4*>(Wloop + (size_t)(kb - KA) * 128 + bn); \
    }                                                                            \
} while (0)

#define STORE_STAGE(ST) do {                                                     \
    _Pragma("unroll")                                                            \
    for (int j = 0; j < 2; j++) {                                                \
        const int lr = lrow0 + 64 * j;                                           \
        As[ST][lr][ac + 0] = f2tf(pa[j].x);                                      \
        As[ST][lr][ac + 1] = f2tf(pa[j].y);                                      \
        As[ST][lr][ac + 2] = f2tf(pa[j].z);                                      \
        As[ST][lr][ac + 3] = f2tf(pa[j].w);                                      \
        const int kr = bk0 + 8 * j;                                              \
        Bs[ST][kr][bn + 0] = f2tf(pb[j].x);                                      \
        Bs[ST][kr][bn + 1] = f2tf(pb[j].y);                                      \
        Bs[ST][kr][bn + 2] = f2tf(pb[j].z);                                      \
        Bs[ST][kr][bn + 3] = f2tf(pb[j].w);                                      \
    }                                                                            \
} while (0)

#define MMA(CC, A0, A1, A2, A3, B0, B1)                                          \
    asm volatile(                                                                \
        "mma.sync.aligned.m16n8k8.row.col.f32.tf32.tf32.f32 "                    \
        "{%0,%1,%2,%3}, {%4,%5,%6,%7}, {%8,%9}, {%0,%1,%2,%3};\n"                \
        : "+f"(CC[0]), "+f"(CC[1]), "+f"(CC[2]), "+f"(CC[3])                     \
        : "r"(A0), "r"(A1), "r"(A2), "r"(A3), "r"(B0), "r"(B1))

#define COMPUTE_STAGE(ST) do {                                                   \
    _Pragma("unroll")                                                            \
    for (int s = 0; s < 2; s++) {                                                \
        const int kk = s * 8;                                                    \
        uint32_t a[4][4], b[4][2];                                               \
        _Pragma("unroll")                                                        \
        for (int mt = 0; mt < 4; mt++) {                                         \
            const int r = wm * 64 + mt * 16 + g;                                 \
            a[mt][0] = As[ST][r][kk + t];                                        \
            a[mt][1] = As[ST][r + 8][kk + t];                                    \
            a[mt][2] = As[ST][r][kk + t + 4];                                    \
            a[mt][3] = As[ST][r + 8][kk + t + 4];                                \
        }                                                                        \
        _Pragma("unroll")                                                        \
        for (int nt = 0; nt < 4; nt++) {                                         \
            const int cn = wn * 32 + nt * 8 + g;                                 \
            b[nt][0] = Bs[ST][kk + t][cn];                                       \
            b[nt][1] = Bs[ST][kk + t + 4][cn];                                   \
        }                                                                        \
        _Pragma("unroll")                                                        \
        for (int mt = 0; mt < 4; mt++)                                           \
            _Pragma("unroll")                                                    \
            for (int nt = 0; nt < 4; nt++)                                       \
                MMA(c[mt][nt], a[mt][0], a[mt][1], a[mt][2], a[mt][3],           \
                    b[nt][0], b[nt][1]);                                         \
    }                                                                            \
} while (0)

    PREFETCH(0);
    STORE_STAGE(0);
    __syncthreads();

    const int NIT = KTOT / 16;   // 72
    for (int it = 0; it < NIT; it++) {
        const int st = it & 1;
        if (it < NIT - 1) {
            const int k0n = (it + 1) * 16;
            PREFETCH(k0n);
        }
        COMPUTE_STAGE(st);
        if (it < NIT - 1) {
            STORE_STAGE(st ^ 1);
            __syncthreads();
        }
    }

    // Epilogue: bias + relu + store (float2 per c-pair)
    #pragma unroll
    for (int mt = 0; mt < 4; mt++) {
        const int r0 = n0blk + wm * 64 + mt * 16 + g;
        const int r1 = r0 + 8;
        #pragma unroll
        for (int nt = 0; nt < 4; nt++) {
            const int cn = wn * 32 + nt * 8 + 2 * t;
            const float b0 = bias_s[cn], b1 = bias_s[cn + 1];
            if (r0 < N_NODES) {
                float2 v;
                v.x = fmaxf(c[mt][nt][0] + b0, 0.f);
                v.y = fmaxf(c[mt][nt][1] + b1, 0.f);
                *reinterpret_cast<float2*>(out + (size_t)r0 * 128 + cn) = v;
            }
            if (r1 < N_NODES) {
                float2 v;
                v.x = fmaxf(c[mt][nt][2] + b0, 0.f);
                v.y = fmaxf(c[mt][nt][3] + b1, 0.f);
                *reinterpret_cast<float2*>(out + (size_t)r1 * 128 + cn) = v;
            }
        }
    }
}

// ---------------------------------------------------------------------------
// Launch. Inputs: 0:x 1:edge_weight 2:W_lin 3:b_lin 4:W_loop 5:b_loop
//                 6:node_in 7:node_out 8:relation
// ---------------------------------------------------------------------------
extern "C" void kernel_launch(void* const* d_in, const int* in_sizes, int n_in,
                              void* d_out, int out_size) {
    const float* x     = (const float*)d_in[0];
    const float* ew    = (const float*)d_in[1];
    const float* Wlin  = (const float*)d_in[2];
    const float* blin  = (const float*)d_in[3];
    const float* Wloop = (const float*)d_in[4];
    const float* bloop = (const float*)d_in[5];
    const int* nin     = (const int*)d_in[6];
    const int* nout    = (const int*)d_in[7];
    const int* rel     = (const int*)d_in[8];
    float* out         = (float*)d_out;

    zero_kernel<<<4096, 256>>>();
    scatter_kernel<<<E_EDGES / 8, 256>>>(x, ew, nin, nout, rel);
    invden_kernel<<<(NR + 255) / 256, 256>>>();
    gemm_tf32<<<(N_NODES + 127) / 128, 256>>>(x, Wlin, blin, Wloop, bloop, out);
}

// round 5
// speedup vs baseline: 2.4024x; 1.1223x over previous
#include <cuda_runtime.h>
#include <cstdint>

#define N_NODES 50000
#define D 128
#define R_REL 8
#define E_EDGES 800000
#define NR (N_NODES * R_REL)   // 400000
#define KTOT 1152              // R*D + D
#define KA 1024                // R*D

#define SCAN_BLK 4096          // elements per scan block (256 thr x 16)
#define NSCAN ((NR + SCAN_BLK - 1) / SCAN_BLK)   // 98

// Scratch (__device__ globals; no allocation allowed)
__device__ float g_num[(size_t)N_NODES * 1024];  // [N*R, D] pre-scaled segment means
__device__ int g_cnt[NR];                        // per-segment edge count
__device__ int g_cur[NR];                        // fill cursors
__device__ int g_off[NR];                        // CSR offsets (exclusive scan of cnt)
__device__ int g_bsum[NSCAN + 1];                // scan block sums
__device__ int g_eidx[E_EDGES];                  // edge ids sorted by segment

// ---------------------------------------------------------------------------
// Zero counters (tiny: 3.2 MB)
// ---------------------------------------------------------------------------
__global__ void zero_cnt_kernel() {
    const int i = blockIdx.x * blockDim.x + threadIdx.x;
    if (i < NR) { g_cnt[i] = 0; g_cur[i] = 0; }
}

// ---------------------------------------------------------------------------
// Histogram: count edges per segment
// ---------------------------------------------------------------------------
__global__ void hist_kernel(const int* __restrict__ nout, const int* __restrict__ rel) {
    const int e = blockIdx.x * blockDim.x + threadIdx.x;
    if (e < E_EDGES) atomicAdd(&g_cnt[nout[e] * R_REL + rel[e]], 1);
}

// ---------------------------------------------------------------------------
// Exclusive scan of g_cnt -> g_off (3 kernels)
// ---------------------------------------------------------------------------
__global__ void scan1_kernel() {
    __shared__ int sd[256];
    const int t = threadIdx.x;
    const int base = blockIdx.x * SCAN_BLK + t * 16;
    int v[16], sum = 0;
    #pragma unroll
    for (int j = 0; j < 16; j++) {
        v[j] = sum;
        const int idx = base + j;
        sum += (idx < NR) ? g_cnt[idx] : 0;
    }
    sd[t] = sum;
    __syncthreads();
    #pragma unroll
    for (int d = 1; d < 256; d <<= 1) {
        int val = sd[t];
        if (t >= d) val += sd[t - d];
        __syncthreads();
        sd[t] = val;
        __syncthreads();
    }
    const int excl = sd[t] - sum;
    #pragma unroll
    for (int j = 0; j < 16; j++) {
        const int idx = base + j;
        if (idx < NR) g_off[idx] = excl + v[j];
    }
    if (t == 255) g_bsum[blockIdx.x] = sd[255];
}

__global__ void scan2_kernel() {
    __shared__ int sd[128];
    const int t = threadIdx.x;
    const int orig = (t < NSCAN) ? g_bsum[t] : 0;
    sd[t] = orig;
    __syncthreads();
    #pragma unroll
    for (int d = 1; d < 128; d <<= 1) {
        int val = sd[t];
        if (t >= d) val += sd[t - d];
        __syncthreads();
        sd[t] = val;
        __syncthreads();
    }
    if (t < NSCAN) g_bsum[t] = sd[t] - orig;   // exclusive
}

__global__ void scan3_kernel() {
    const int i = blockIdx.x * blockDim.x + threadIdx.x;
    if (i < NR) g_off[i] += g_bsum[i / SCAN_BLK];
}

// ---------------------------------------------------------------------------
// Fill sorted edge-id lists
// ---------------------------------------------------------------------------
__global__ void fill_kernel(const int* __restrict__ nout, const int* __restrict__ rel) {
    const int e = blockIdx.x * blockDim.x + threadIdx.x;
    if (e >= E_EDGES) return;
    const int seg = nout[e] * R_REL + rel[e];
    const int pos = g_off[seg] + atomicAdd(&g_cur[seg], 1);
    g_eidx[pos] = e;
}

// ---------------------------------------------------------------------------
// Aggregate: warp per segment, no atomics, write scaled mean once.
// ---------------------------------------------------------------------------
__global__ void aggregate_kernel(const float* __restrict__ x,
                                 const float* __restrict__ ew,
                                 const int* __restrict__ nin) {
    const int seg = (blockIdx.x * blockDim.x + threadIdx.x) >> 5;
    const int lane = threadIdx.x & 31;
    if (seg >= NR) return;

    const int start = g_off[seg];
    const int cnt = g_cnt[seg];

    float4 acc = make_float4(0.f, 0.f, 0.f, 0.f);
    float den = 0.f;
    int i = 0;
    for (; i + 2 <= cnt; i += 2) {   // 2-way for MLP
        const int e0 = g_eidx[start + i];
        const int e1 = g_eidx[start + i + 1];
        const float w0 = ew[e0], w1 = ew[e1];
        const int v0 = nin[e0], v1 = nin[e1];
        const float4 x0 = *reinterpret_cast<const float4*>(x + (size_t)v0 * D + lane * 4);
        const float4 x1 = *reinterpret_cast<const float4*>(x + (size_t)v1 * D + lane * 4);
        acc.x += w0 * x0.x + w1 * x1.x;
        acc.y += w0 * x0.y + w1 * x1.y;
        acc.z += w0 * x0.z + w1 * x1.z;
        acc.w += w0 * x0.w + w1 * x1.w;
        den += w0 + w1;
    }
    if (i < cnt) {
        const int e0 = g_eidx[start + i];
        const float w0 = ew[e0];
        const int v0 = nin[e0];
        const float4 x0 = *reinterpret_cast<const float4*>(x + (size_t)v0 * D + lane * 4);
        acc.x += w0 * x0.x; acc.y += w0 * x0.y;
        acc.z += w0 * x0.z; acc.w += w0 * x0.w;
        den += w0;
    }
    const float s = 1.0f / (den + 1e-10f);
    float4 o;
    o.x = acc.x * s; o.y = acc.y * s; o.z = acc.z * s; o.w = acc.w * s;
    *reinterpret_cast<float4*>(g_num + (size_t)seg * D + lane * 4) = o;
}

// ---------------------------------------------------------------------------
// TF32 tensor-core GEMM (round-2 proven kernel; A now pre-scaled):
// out = relu( [g_num | x] @ [W_lin ; W_loop] + b_lin + b_loop )
// BM=BN=128, BK=16, 256 threads (2x4 warps, warp tile 64x32),
// mma.sync.m16n8k8.tf32, double-buffered smem.
// ---------------------------------------------------------------------------
#define AS_STRIDE 20
#define BS_STRIDE 136

__device__ __forceinline__ uint32_t f2tf(float f) {
    uint32_t u;
    asm("cvt.rna.tf32.f32 %0, %1;" : "=r"(u) : "f"(f));
    return u;
}

__global__ __launch_bounds__(256, 2)
void gemm_tf32(const float* __restrict__ x,
               const float* __restrict__ Wlin, const float* __restrict__ blin,
               const float* __restrict__ Wloop, const float* __restrict__ bloop,
               float* __restrict__ out) {
    __shared__ uint32_t As[2][128][AS_STRIDE];
    __shared__ uint32_t Bs[2][16][BS_STRIDE];
    __shared__ float bias_s[128];

    const int tid  = threadIdx.x;
    const int n0blk = blockIdx.x * 128;

    if (tid < 128) bias_s[tid] = blin[tid] + bloop[tid];

    const int lane = tid & 31;
    const int wid  = tid >> 5;
    const int g = lane >> 2;
    const int t = lane & 3;
    const int wm = wid >> 2;
    const int wn = wid & 3;

    const int lrow0 = tid >> 2;
    const int ac    = (tid & 3) * 4;
    const int bk0   = tid >> 5;
    const int bn    = lane * 4;

    float c[4][4][4];
    #pragma unroll
    for (int mt = 0; mt < 4; mt++)
        #pragma unroll
        for (int nt = 0; nt < 4; nt++)
            #pragma unroll
            for (int q = 0; q < 4; q++) c[mt][nt][q] = 0.f;

    float4 pa[2], pb[2];

#define PREFETCH(K0) do {                                                        \
    _Pragma("unroll")                                                            \
    for (int j = 0; j < 2; j++) {                                                \
        const int lr = lrow0 + 64 * j;                                           \
        const int gr = n0blk + lr;                                               \
        float4 v = make_float4(0.f, 0.f, 0.f, 0.f);                              \
        if (gr < N_NODES) {                                                      \
            v = ((K0) < KA)                                                      \
              ? *reinterpret_cast<const float4*>(g_num + (size_t)gr * 1024 + (K0) + ac) \
              : *reinterpret_cast<const float4*>(x + (size_t)gr * 128 + (K0) - KA + ac); \
        }                                                                        \
        pa[j] = v;                                                               \
        const int kb = (K0) + bk0 + 8 * j;                                       \
        pb[j] = (kb < KA)                                                        \
            ? *reinterpret_cast<const float4*>(Wlin + (size_t)kb * 128 + bn)     \
            : *reinterpret_cast<const float4*>(Wloop + (size_t)(kb - KA) * 128 + bn); \
    }                                                                            \
} while (0)

#define STORE_STAGE(ST) do {                                                     \
    _Pragma("unroll")                                                            \
    for (int j = 0; j < 2; j++) {                                                \
        const int lr = lrow0 + 64 * j;                                           \
        As[ST][lr][ac + 0] = f2tf(pa[j].x);                                      \
        As[ST][lr][ac + 1] = f2tf(pa[j].y);                                      \
        As[ST][lr][ac + 2] = f2tf(pa[j].z);                                      \
        As[ST][lr][ac + 3] = f2tf(pa[j].w);                                      \
        const int kr = bk0 + 8 * j;                                              \
        Bs[ST][kr][bn + 0] = f2tf(pb[j].x);                                      \
        Bs[ST][kr][bn + 1] = f2tf(pb[j].y);                                      \
        Bs[ST][kr][bn + 2] = f2tf(pb[j].z);                                      \
        Bs[ST][kr][bn + 3] = f2tf(pb[j].w);                                      \
    }                                                                            \
} while (0)

#define MMA(CC, A0, A1, A2, A3, B0, B1)                                          \
    asm volatile(                                                                \
        "mma.sync.aligned.m16n8k8.row.col.f32.tf32.tf32.f32 "                    \
        "{%0,%1,%2,%3}, {%4,%5,%6,%7}, {%8,%9}, {%0,%1,%2,%3};\n"                \
        : "+f"(CC[0]), "+f"(CC[1]), "+f"(CC[2]), "+f"(CC[3])                     \
        : "r"(A0), "r"(A1), "r"(A2), "r"(A3), "r"(B0), "r"(B1))

#define COMPUTE_STAGE(ST) do {                                                   \
    _Pragma("unroll")                                                            \
    for (int s = 0; s < 2; s++) {                                                \
        const int kk = s * 8;                                                    \
        uint32_t a[4][4], b[4][2];                                               \
        _Pragma("unroll")                                                        \
        for (int mt = 0; mt < 4; mt++) {                                         \
            const int r = wm * 64 + mt * 16 + g;                                 \
            a[mt][0] = As[ST][r][kk + t];                                        \
            a[mt][1] = As[ST][r + 8][kk + t];                                    \
            a[mt][2] = As[ST][r][kk + t + 4];                                    \
            a[mt][3] = As[ST][r + 8][kk + t + 4];                                \
        }                                                                        \
        _Pragma("unroll")                                                        \
        for (int nt = 0; nt < 4; nt++) {                                         \
            const int cn = wn * 32 + nt * 8 + g;                                 \
            b[nt][0] = Bs[ST][kk + t][cn];                                       \
            b[nt][1] = Bs[ST][kk + t + 4][cn];                                   \
        }                                                                        \
        _Pragma("unroll")                                                        \
        for (int mt = 0; mt < 4; mt++)                                           \
            _Pragma("unroll")                                                    \
            for (int nt = 0; nt < 4; nt++)                                       \
                MMA(c[mt][nt], a[mt][0], a[mt][1], a[mt][2], a[mt][3],           \
                    b[nt][0], b[nt][1]);                                         \
    }                                                                            \
} while (0)

    PREFETCH(0);
    STORE_STAGE(0);
    __syncthreads();

    const int NIT = KTOT / 16;   // 72
    for (int it = 0; it < NIT; it++) {
        const int st = it & 1;
        if (it < NIT - 1) {
            const int k0n = (it + 1) * 16;
            PREFETCH(k0n);
        }
        COMPUTE_STAGE(st);
        if (it < NIT - 1) {
            STORE_STAGE(st ^ 1);
            __syncthreads();
        }
    }

    #pragma unroll
    for (int mt = 0; mt < 4; mt++) {
        const int r0 = n0blk + wm * 64 + mt * 16 + g;
        const int r1 = r0 + 8;
        #pragma unroll
        for (int nt = 0; nt < 4; nt++) {
            const int cn = wn * 32 + nt * 8 + 2 * t;
            const float b0 = bias_s[cn], b1 = bias_s[cn + 1];
            if (r0 < N_NODES) {
                float2 v;
                v.x = fmaxf(c[mt][nt][0] + b0, 0.f);
                v.y = fmaxf(c[mt][nt][1] + b1, 0.f);
                *reinterpret_cast<float2*>(out + (size_t)r0 * 128 + cn) = v;
            }
            if (r1 < N_NODES) {
                float2 v;
                v.x = fmaxf(c[mt][nt][2] + b0, 0.f);
                v.y = fmaxf(c[mt][nt][3] + b1, 0.f);
                *reinterpret_cast<float2*>(out + (size_t)r1 * 128 + cn) = v;
            }
        }
    }
}

// ---------------------------------------------------------------------------
// Launch. Inputs: 0:x 1:edge_weight 2:W_lin 3:b_lin 4:W_loop 5:b_loop
//                 6:node_in 7:node_out 8:relation
// ---------------------------------------------------------------------------
extern "C" void kernel_launch(void* const* d_in, const int* in_sizes, int n_in,
                              void* d_out, int out_size) {
    const float* x     = (const float*)d_in[0];
    const float* ew    = (const float*)d_in[1];
    const float* Wlin  = (const float*)d_in[2];
    const float* blin  = (const float*)d_in[3];
    const float* Wloop = (const float*)d_in[4];
    const float* bloop = (const float*)d_in[5];
    const int* nin     = (const int*)d_in[6];
    const int* nout    = (const int*)d_in[7];
    const int* rel     = (const int*)d_in[8];
    float* out         = (float*)d_out;

    zero_cnt_kernel<<<(NR + 255) / 256, 256>>>();
    hist_kernel<<<(E_EDGES + 255) / 256, 256>>>(nout, rel);
    scan1_kernel<<<NSCAN, 256>>>();
    scan2_kernel<<<1, 128>>>();
    scan3_kernel<<<(NR + 255) / 256, 256>>>();
    fill_kernel<<<(E_EDGES + 255) / 256, 256>>>(nout, rel);
    aggregate_kernel<<<NR / 8, 256>>>(x, ew, nin);
    gemm_tf32<<<(N_NODES + 127) / 128, 256>>>(x, Wlin, blin, Wloop, bloop, out);
}